// round 1
// baseline (speedup 1.0000x reference)
#include <cuda_runtime.h>
#include <cstdint>

// Problem dims (fixed instance)
#define V    2048
#define NB   16
#define DI   32
#define DO   64
#define NH   8
#define NPJ  (V*NB)           // 32768
#define ACT_ROWS (NH*12*12)   // 1152
#define CI   (DI*6)           // 192

// ------------------------- device scratch -------------------------
__device__ float g_cross[CI*NPJ];        // [ci][p*16+j]          25.2 MB
__device__ float g_act[ACT_ROWS*NPJ];    // [(h,k,r)][p*16+j]    151 MB
__device__ float g_nfm[144*CI*V];        // [(k,r)][ci][p]       226 MB
__device__ float g_feat[144*DO*V];       // [(k,r)][d][p]         75 MB
__device__ float g_M[ACT_ROWS*CI];       // act weights (1152x192)
__device__ float g_Wf[144*DO*CI];        // feat weights per (k,r)
__device__ float g_Wc[12*DO*CI];         // center weights per r
__device__ float g_fmT[CI*V];            // feature_map transposed [ci][p]

// ------------------------- constants -------------------------
__constant__ float c_VS[12][3] = {
 {0.f, 0.5257311121f, 0.8506508084f},
 {0.f, 0.5257311121f,-0.8506508084f},
 {0.f,-0.5257311121f, 0.8506508084f},
 {0.f,-0.5257311121f,-0.8506508084f},
 { 0.5257311121f, 0.8506508084f,0.f},
 { 0.5257311121f,-0.8506508084f,0.f},
 {-0.5257311121f, 0.8506508084f,0.f},
 {-0.5257311121f,-0.8506508084f,0.f},
 { 0.8506508084f,0.f, 0.5257311121f},
 { 0.8506508084f,0.f,-0.5257311121f},
 {-0.8506508084f,0.f, 0.5257311121f},
 {-0.8506508084f,0.f,-0.5257311121f}};

__constant__ int c_C2V[6][2] = {{0,1},{6,7},{2,11},{4,9},{5,8},{3,10}};

// inverse color permutations (argsort of _COLOR_COM rows)
__constant__ int c_INV[12][6] = {
 {0,1,2,3,4,5},{0,5,4,3,2,1},{4,3,0,5,2,1},{1,2,4,3,5,0},
 {3,5,2,0,4,1},{1,4,3,5,0,2},{4,0,3,1,2,5},{1,0,2,4,3,5},
 {4,1,2,5,0,3},{3,1,4,0,2,5},{2,1,4,5,3,0},{4,5,0,3,1,2}};

__constant__ int c_ROLL[5][6] = {
 {0,1,2,3,4,5},{0,2,3,4,5,1},{0,3,4,5,1,2},{0,4,5,1,2,3},{0,5,1,2,3,4}};

// W13[k][m] from 18 raw params
__device__ __forceinline__ float w13(const float* __restrict__ Wp, int k, int m) {
    if (k == 0)  return (m == 0) ? Wp[0] : Wp[1];
    if (k == 1)  return (m == 0) ? Wp[2] : Wp[3];
    if (k == 12) return (m == 0) ? Wp[4] : Wp[5];
    int pp = (k - 2) / 5, s = (k - 2) % 5;
    return Wp[6 + pp * 6 + c_ROLL[s][m]];
}

// ------------------------- K0: weight expansion + fm transpose -------------------------
__global__ void k0_weights(const float* __restrict__ W, const float* __restrict__ Wdir,
                           const float* __restrict__ fm) {
    const int N1 = ACT_ROWS * CI;          // 221184
    const int N2 = 144 * DO * CI;          // 1769472
    const int N3 = 12 * DO * CI;           // 147456
    const int N4 = CI * V;                 // 393216
    const int total = N1 + N2 + N3 + N4;
    for (int idx = blockIdx.x * blockDim.x + threadIdx.x; idx < total;
         idx += gridDim.x * blockDim.x) {
        if (idx < N1) {
            int ci = idx % CI, row = idx / CI;
            int r = row % 12, hk = row / 12, k = hk % 12, h = hk / 12;
            int c = ci / 6, i = ci % 6;
            g_M[idx] = w13(Wdir + (h * DI + c) * 18, k, c_INV[r][i]);
        } else if (idx < N1 + N2) {
            int j = idx - N1;
            int ci = j % CI, dj = j / CI, d = dj % DO, kr = dj / DO;
            int r = kr % 12, k = kr / 12;
            g_Wf[j] = w13(W + (d * DI + ci / 6) * 18, k, c_INV[r][ci % 6]);
        } else if (idx < N1 + N2 + N3) {
            int j = idx - N1 - N2;
            int ci = j % CI, dj = j / CI, d = dj % DO, r = dj / DO;
            g_Wc[j] = w13(W + (d * DI + ci / 6) * 18, 12, c_INV[r][ci % 6]);
        } else {
            int j = idx - N1 - N2 - N3;
            int p = j % V, ci = j / V;
            g_fmT[j] = fm[((ci / 6) * V + p) * 6 + (ci % 6)];
        }
    }
}

// ------------------------- K1: per-vertex cross features -------------------------
// cross[o,p,j,i] = sum_{c=0..32} W_dim[c,o] * [nf | de6][c,p,j,i]
__global__ void k1_cross(const int* __restrict__ nbr, const float* __restrict__ verts,
                         const float* __restrict__ fm, const float* __restrict__ Wdim) {
    int p = blockIdx.x;
    int t = threadIdx.x;   // 192 threads
    __shared__ int   s_nbr[NB];
    __shared__ float s_cin[DI + 1][NB][6];
    __shared__ float s_wd[(DI + 1) * DI];
    if (t < NB) s_nbr[t] = nbr[p * NB + t];
    for (int x = t; x < (DI + 1) * DI; x += 192) s_wd[x] = Wdim[x];
    __syncthreads();
    if (t < NB) {
        int q = s_nbr[t];
        float cx = verts[p * 3], cy = verts[p * 3 + 1], cz = verts[p * 3 + 2];
        float dx = verts[q * 3] - cx, dy = verts[q * 3 + 1] - cy, dz = verts[q * 3 + 2] - cz;
        float nrm = fmaxf(sqrtf(dx * dx + dy * dy + dz * dz), 1e-12f);
        dx /= nrm; dy /= nrm; dz /= nrm;
        float de[12];
        #pragma unroll
        for (int v = 0; v < 12; v++)
            de[v] = c_VS[v][0] * dx + c_VS[v][1] * dy + c_VS[v][2] * dz;
        #pragma unroll
        for (int i = 0; i < 6; i++)
            s_cin[DI][t][i] = fmaxf(de[c_C2V[i][0]], de[c_C2V[i][1]]);
    }
    for (int x = t; x < DI * NB * 6; x += 192) {
        int c = x / (NB * 6), rem = x % (NB * 6), j = rem / 6, i = rem % 6;
        s_cin[c][j][i] = fm[(c * V + s_nbr[j]) * 6 + i];
    }
    __syncthreads();
    int o = t / 6, i = t % 6;
    for (int j = 0; j < NB; j++) {
        float a = 0.f;
        #pragma unroll
        for (int c = 0; c <= DI; c++) a += s_wd[c * DI + o] * s_cin[c][j][i];
        g_cross[(o * 6 + i) * NPJ + p * NB + j] = a;
    }
}

// ------------------------- K2: act logits SGEMM (1152 x 32768 x 192) -------------------------
__global__ void k2_gemm() {
    const float* __restrict__ A = g_M;      // 1152 x 192
    const float* __restrict__ B = g_cross;  // 192 x 32768
    float* __restrict__ C = g_act;
    __shared__ float As[16][128];
    __shared__ float Bs[16][128];
    int tid = threadIdx.x;                  // 256
    int n0 = blockIdx.x * 128, m0 = blockIdx.y * 128;
    int tx = tid % 16, ty = tid / 16;
    int arow = tid / 4, acol4 = (tid % 4) * 4;
    int brow = tid / 32, bcol4 = (tid % 32) * 4;
    float acc[8][8] = {};
    for (int kt = 0; kt < CI; kt += 16) {
        #pragma unroll
        for (int q = 0; q < 2; q++) {
            int r = arow + q * 64;
            float4 vv = *(const float4*)(A + (m0 + r) * CI + kt + acol4);
            As[acol4 + 0][r] = vv.x; As[acol4 + 1][r] = vv.y;
            As[acol4 + 2][r] = vv.z; As[acol4 + 3][r] = vv.w;
        }
        #pragma unroll
        for (int q = 0; q < 2; q++) {
            int r = brow + q * 8;
            *(float4*)(&Bs[r][bcol4]) = *(const float4*)(B + (size_t)(kt + r) * NPJ + n0 + bcol4);
        }
        __syncthreads();
        #pragma unroll
        for (int kk = 0; kk < 16; kk++) {
            float a[8], b[8];
            #pragma unroll
            for (int u = 0; u < 8; u++) a[u] = As[kk][ty * 8 + u];
            #pragma unroll
            for (int u = 0; u < 8; u++) b[u] = Bs[kk][tx * 8 + u];
            #pragma unroll
            for (int um = 0; um < 8; um++)
                #pragma unroll
                for (int un = 0; un < 8; un++) acc[um][un] += a[um] * b[un];
        }
        __syncthreads();
    }
    #pragma unroll
    for (int um = 0; um < 8; um++) {
        int row = m0 + ty * 8 + um;
        #pragma unroll
        for (int un = 0; un < 8; un += 4) {
            float4 vv = make_float4(acc[um][un] * 0.5f, acc[um][un + 1] * 0.5f,
                                    acc[um][un + 2] * 0.5f, acc[um][un + 3] * 0.5f);
            *(float4*)(C + (size_t)row * NPJ + n0 + tx * 8 + un) = vv;
        }
    }
}

// ------------------------- K3: softmax over the 16 neighbors -------------------------
__global__ void k3_softmax() {
    int idx = blockIdx.x * blockDim.x + threadIdx.x;
    if (idx >= ACT_ROWS * V) return;
    float4* g = (float4*)(g_act + (size_t)idx * NB);
    float v[16];
    #pragma unroll
    for (int q = 0; q < 4; q++) {
        float4 t = g[q];
        v[q * 4 + 0] = t.x; v[q * 4 + 1] = t.y; v[q * 4 + 2] = t.z; v[q * 4 + 3] = t.w;
    }
    float mx = v[0];
    #pragma unroll
    for (int j = 1; j < 16; j++) mx = fmaxf(mx, v[j]);
    float s = 0.f;
    #pragma unroll
    for (int j = 0; j < 16; j++) { v[j] = __expf(v[j] - mx); s += v[j]; }
    float inv = 1.f / s;
    #pragma unroll
    for (int q = 0; q < 4; q++) {
        float4 t = make_float4(v[q*4] * inv, v[q*4+1] * inv, v[q*4+2] * inv, v[q*4+3] * inv);
        g[q] = t;
    }
}

// ------------------------- K4a: nfm[(k,r)][ci][p] = sum_j act*cross -------------------------
__global__ void k4a_nfm() {
    int k = blockIdx.y;                    // 0..11
    int tid = threadIdx.x;                 // 512
    int pl = tid & 127, cg = tid >> 7;     // 128 p-lanes, 4 ci-lanes
    int p = blockIdx.x * 128 + pl;
    for (int ci = cg; ci < CI; ci += 4) {
        int c = ci / 6, h = c >> 2;
        const float4* xb = (const float4*)(g_cross + (size_t)ci * NPJ + p * NB);
        float4 x0 = xb[0], x1 = xb[1], x2 = xb[2], x3 = xb[3];
        int abase = (h * 12 + k) * 12;
        #pragma unroll
        for (int r = 0; r < 12; r++) {
            const float4* ar = (const float4*)(g_act + (size_t)(abase + r) * NPJ + p * NB);
            float4 a0 = ar[0], a1 = ar[1], a2 = ar[2], a3 = ar[3];
            float acc = a0.x*x0.x + a0.y*x0.y + a0.z*x0.z + a0.w*x0.w
                      + a1.x*x1.x + a1.y*x1.y + a1.z*x1.z + a1.w*x1.w
                      + a2.x*x2.x + a2.y*x2.y + a2.z*x2.z + a2.w*x2.w
                      + a3.x*x3.x + a3.y*x3.y + a3.z*x3.z + a3.w*x3.w;
            g_nfm[((size_t)(k * 12 + r) * CI + ci) * V + p] = acc;
        }
    }
}

// ------------------------- K4b: feat[(k,r)][d][p] = Wf_kr (64x192) @ nfm_kr (192x2048) ----
__global__ void k4b_feat() {
    int kr = blockIdx.y;                   // 0..143
    int p0 = blockIdx.x * 128;             // 16 tiles
    const float* __restrict__ A = g_Wf + (size_t)kr * DO * CI;   // 64x192
    const float* __restrict__ B = g_nfm + (size_t)kr * CI * V;   // 192x2048
    __shared__ float As[16][64];
    __shared__ float Bs[16][128];
    int tid = threadIdx.x;                 // 128
    int tx = tid % 16, ty = tid / 16;      // ty 0..7 (d), tx 0..15 (p)
    float acc[8][8] = {};
    for (int kt = 0; kt < CI; kt += 16) {
        #pragma unroll
        for (int q = 0; q < 2; q++) {      // A: 64x16 = 256 float4
            int li = q * 128 + tid;
            int row = li / 4, col4 = (li % 4) * 4;
            float4 vv = *(const float4*)(A + row * CI + kt + col4);
            As[col4 + 0][row] = vv.x; As[col4 + 1][row] = vv.y;
            As[col4 + 2][row] = vv.z; As[col4 + 3][row] = vv.w;
        }
        #pragma unroll
        for (int q = 0; q < 4; q++) {      // B: 16x128 = 512 float4
            int li = q * 128 + tid;
            int row = li / 32, col4 = (li % 32) * 4;
            *(float4*)(&Bs[row][col4]) = *(const float4*)(B + (size_t)(kt + row) * V + p0 + col4);
        }
        __syncthreads();
        #pragma unroll
        for (int kk = 0; kk < 16; kk++) {
            float a[8], b[8];
            #pragma unroll
            for (int u = 0; u < 8; u++) a[u] = As[kk][ty * 8 + u];
            #pragma unroll
            for (int u = 0; u < 8; u++) b[u] = Bs[kk][tx * 8 + u];
            #pragma unroll
            for (int um = 0; um < 8; um++)
                #pragma unroll
                for (int un = 0; un < 8; un++) acc[um][un] += a[um] * b[un];
        }
        __syncthreads();
    }
    #pragma unroll
    for (int um = 0; um < 8; um++) {
        int d = ty * 8 + um;
        #pragma unroll
        for (int un = 0; un < 8; un += 4) {
            float4 vv = make_float4(acc[um][un], acc[um][un+1], acc[um][un+2], acc[um][un+3]);
            *(float4*)(g_feat + ((size_t)kr * DO + d) * V + p0 + tx * 8 + un) = vv;
        }
    }
}

// ------------------------- K5: center + k-sum + color-pair max + fm copy ----------------
__global__ void k5_final(const float* __restrict__ fm, float* __restrict__ out) {
    int idx = blockIdx.x * blockDim.x + threadIdx.x;
    const int NKA = DO * V;                // 131072
    if (idx < NKA) {
        int d = idx / V, p = idx % V;
        float ka[12];
        #pragma unroll
        for (int r = 0; r < 12; r++) ka[r] = 0.f;
        // center: ka[r] += sum_ci Wc[r][d][ci] * fmT[ci][p]
        for (int ci = 0; ci < CI; ci++) {
            float x = g_fmT[ci * V + p];
            #pragma unroll
            for (int r = 0; r < 12; r++)
                ka[r] += g_Wc[(r * DO + d) * CI + ci] * x;
        }
        // sum over k slots
        #pragma unroll
        for (int k = 0; k < 12; k++)
            #pragma unroll
            for (int r = 0; r < 12; r++)
                ka[r] += g_feat[((size_t)(k * 12 + r) * DO + d) * V + p];
        #pragma unroll
        for (int cc = 0; cc < 6; cc++)
            out[d * (V * 6) + p * 6 + cc] = fmaxf(ka[c_C2V[cc][0]], ka[c_C2V[cc][1]]);
    } else {
        int j = idx - NKA;
        if (j < DI * V * 6)
            out[DO * V * 6 + j] = fm[j];
    }
}

// ------------------------- launch -------------------------
extern "C" void kernel_launch(void* const* d_in, const int* in_sizes, int n_in,
                              void* d_out, int out_size) {
    const int*   nbr   = (const int*)d_in[0];
    const float* verts = (const float*)d_in[1];
    const float* fm    = (const float*)d_in[2];
    const float* Wdim  = (const float*)d_in[3];
    const float* W     = (const float*)d_in[4];
    const float* Wdir  = (const float*)d_in[5];
    float* out = (float*)d_out;

    k0_weights<<<512, 256>>>(W, Wdir, fm);
    k1_cross<<<V, 192>>>(nbr, verts, fm, Wdim);
    k2_gemm<<<dim3(NPJ / 128, ACT_ROWS / 128), 256>>>();
    k3_softmax<<<(ACT_ROWS * V + 255) / 256, 256>>>();
    k4a_nfm<<<dim3(V / 128, 12), 512>>>();
    k4b_feat<<<dim3(V / 128, 144), 128>>>();
    k5_final<<<(DO * V + DI * V * 6 + 255) / 256, 256>>>(fm, out);
}

// round 5
// speedup vs baseline: 1.1721x; 1.1721x over previous
#include <cuda_runtime.h>
#include <cuda_fp16.h>
#include <mma.h>
#include <cstdint>

using namespace nvcuda;

// Problem dims (fixed instance)
#define V    2048
#define NB   16
#define DI   32
#define DO   64
#define NH   8
#define NPJ  (V*NB)           // 32768
#define ACT_ROWS (NH*12*12)   // 1152
#define CI   (DI*6)           // 192

// ------------------------- device scratch -------------------------
__device__ __align__(16) float  g_cross[CI*NPJ];     // fp32 cross [ci][n]      25 MB
__device__ __align__(16) __half g_crossh[CI*NPJ];    // fp16 copy for GEMM      13 MB
__device__ __align__(16) float  g_act[ACT_ROWS*NPJ]; // logits -> act          151 MB
__device__ __align__(16) __half g_nfmh[144*CI*V];    // [(k,r)][ci][p] fp16    113 MB
__device__ __align__(16) float  g_feat[144*DO*V];    // [(k,r)][d][p]           75 MB
__device__ __align__(16) __half g_Mh[ACT_ROWS*CI];   // act weights fp16 (pre-scaled 0.5)
__device__ __align__(16) __half g_Wfh[144*DO*CI];    // feat weights per (k,r) fp16
__device__ __align__(16) float  g_Wc[12*DO*CI];      // center weights fp32
__device__ __align__(16) float  g_fmT[CI*V];         // fm transposed [ci][p]

// ------------------------- constants -------------------------
__constant__ float c_VS[12][3] = {
 {0.f, 0.5257311121f, 0.8506508084f},
 {0.f, 0.5257311121f,-0.8506508084f},
 {0.f,-0.5257311121f, 0.8506508084f},
 {0.f,-0.5257311121f,-0.8506508084f},
 { 0.5257311121f, 0.8506508084f,0.f},
 { 0.5257311121f,-0.8506508084f,0.f},
 {-0.5257311121f, 0.8506508084f,0.f},
 {-0.5257311121f,-0.8506508084f,0.f},
 { 0.8506508084f,0.f, 0.5257311121f},
 { 0.8506508084f,0.f,-0.5257311121f},
 {-0.8506508084f,0.f, 0.5257311121f},
 {-0.8506508084f,0.f,-0.5257311121f}};

__constant__ int c_C2V[6][2] = {{0,1},{6,7},{2,11},{4,9},{5,8},{3,10}};

__constant__ int c_INV[12][6] = {
 {0,1,2,3,4,5},{0,5,4,3,2,1},{4,3,0,5,2,1},{1,2,4,3,5,0},
 {3,5,2,0,4,1},{1,4,3,5,0,2},{4,0,3,1,2,5},{1,0,2,4,3,5},
 {4,1,2,5,0,3},{3,1,4,0,2,5},{2,1,4,5,3,0},{4,5,0,3,1,2}};

__constant__ int c_ROLL[5][6] = {
 {0,1,2,3,4,5},{0,2,3,4,5,1},{0,3,4,5,1,2},{0,4,5,1,2,3},{0,5,1,2,3,4}};

__device__ __forceinline__ float w13(const float* __restrict__ Wp, int k, int m) {
    if (k == 0)  return (m == 0) ? Wp[0] : Wp[1];
    if (k == 1)  return (m == 0) ? Wp[2] : Wp[3];
    if (k == 12) return (m == 0) ? Wp[4] : Wp[5];
    int pp = (k - 2) / 5, s = (k - 2) % 5;
    return Wp[6 + pp * 6 + c_ROLL[s][m]];
}

// ------------------------- K0: weight expansion + fm transpose -------------------------
__global__ void k0_weights(const float* __restrict__ W, const float* __restrict__ Wdir,
                           const float* __restrict__ fm) {
    const int N1 = ACT_ROWS * CI;          // 221184
    const int N2 = 144 * DO * CI;          // 1769472
    const int N3 = 12 * DO * CI;           // 147456
    const int N4 = CI * V;                 // 393216
    const int total = N1 + N2 + N3 + N4;
    for (int idx = blockIdx.x * blockDim.x + threadIdx.x; idx < total;
         idx += gridDim.x * blockDim.x) {
        if (idx < N1) {
            int ci = idx % CI, row = idx / CI;
            int r = row % 12, hk = row / 12, k = hk % 12, h = hk / 12;
            int c = ci / 6, i = ci % 6;
            // fold the 1/sqrt(dph)=0.5 logit scale into the weights (exact)
            g_Mh[idx] = __float2half_rn(0.5f * w13(Wdir + (h * DI + c) * 18, k, c_INV[r][i]));
        } else if (idx < N1 + N2) {
            int j = idx - N1;
            int ci = j % CI, dj = j / CI, d = dj % DO, kr = dj / DO;
            int r = kr % 12, k = kr / 12;
            g_Wfh[j] = __float2half_rn(w13(W + (d * DI + ci / 6) * 18, k, c_INV[r][ci % 6]));
        } else if (idx < N1 + N2 + N3) {
            int j = idx - N1 - N2;
            int ci = j % CI, dj = j / CI, d = dj % DO, r = dj / DO;
            g_Wc[j] = w13(W + (d * DI + ci / 6) * 18, 12, c_INV[r][ci % 6]);
        } else {
            int j = idx - N1 - N2 - N3;
            int p = j % V, ci = j / V;
            g_fmT[j] = fm[((ci / 6) * V + p) * 6 + (ci % 6)];
        }
    }
}

// ------------------------- K1: per-vertex cross features -------------------------
__global__ void k1_cross(const int* __restrict__ nbr, const float* __restrict__ verts,
                         const float* __restrict__ fm, const float* __restrict__ Wdim) {
    int p = blockIdx.x;
    int t = threadIdx.x;   // 192 threads
    __shared__ int   s_nbr[NB];
    __shared__ float s_cin[DI + 1][NB][6];
    __shared__ float s_wd[(DI + 1) * DI];
    if (t < NB) s_nbr[t] = nbr[p * NB + t];
    for (int x = t; x < (DI + 1) * DI; x += 192) s_wd[x] = Wdim[x];
    __syncthreads();
    if (t < NB) {
        int q = s_nbr[t];
        float cx = verts[p * 3], cy = verts[p * 3 + 1], cz = verts[p * 3 + 2];
        float dx = verts[q * 3] - cx, dy = verts[q * 3 + 1] - cy, dz = verts[q * 3 + 2] - cz;
        float nrm = fmaxf(sqrtf(dx * dx + dy * dy + dz * dz), 1e-12f);
        dx /= nrm; dy /= nrm; dz /= nrm;
        float de[12];
        #pragma unroll
        for (int v = 0; v < 12; v++)
            de[v] = c_VS[v][0] * dx + c_VS[v][1] * dy + c_VS[v][2] * dz;
        #pragma unroll
        for (int i = 0; i < 6; i++)
            s_cin[DI][t][i] = fmaxf(de[c_C2V[i][0]], de[c_C2V[i][1]]);
    }
    for (int x = t; x < DI * NB * 6; x += 192) {
        int c = x / (NB * 6), rem = x % (NB * 6), j = rem / 6, i = rem % 6;
        s_cin[c][j][i] = fm[(c * V + s_nbr[j]) * 6 + i];
    }
    __syncthreads();
    int o = t / 6, i = t % 6;
    for (int j = 0; j < NB; j++) {
        float a = 0.f;
        #pragma unroll
        for (int c = 0; c <= DI; c++) a += s_wd[c * DI + o] * s_cin[c][j][i];
        size_t off = (size_t)(o * 6 + i) * NPJ + p * NB + j;
        g_cross[off] = a;
        g_crossh[off] = __float2half_rn(a);
    }
}

// ------------------------- K2: act logits via wmma (1152 x 32768 x 192) -----------------
// Block = 128x128 tile, 8 warps (2x4), warp = 64x32. Fragments loaded straight
// from global (A is L2-resident 0.44MB; B tiles L2-served).
__global__ void k2_wmma() {
    int n0 = blockIdx.x * 128, m0 = blockIdx.y * 128;
    int wid = threadIdx.x >> 5;
    int mBase = m0 + (wid >> 2) * 64;
    int nBase = n0 + (wid & 3) * 32;
    wmma::fragment<wmma::accumulator, 16, 16, 16, float> acc[4][2];
    #pragma unroll
    for (int i = 0; i < 4; i++)
        #pragma unroll
        for (int j = 0; j < 2; j++) wmma::fill_fragment(acc[i][j], 0.0f);
    for (int k = 0; k < CI; k += 16) {
        wmma::fragment<wmma::matrix_a, 16, 16, 16, __half, wmma::row_major> af[4];
        wmma::fragment<wmma::matrix_b, 16, 16, 16, __half, wmma::row_major> bf[2];
        #pragma unroll
        for (int i = 0; i < 4; i++)
            wmma::load_matrix_sync(af[i], g_Mh + (size_t)(mBase + i * 16) * CI + k, CI);
        #pragma unroll
        for (int j = 0; j < 2; j++)
            wmma::load_matrix_sync(bf[j], g_crossh + (size_t)k * NPJ + nBase + j * 16, NPJ);
        #pragma unroll
        for (int i = 0; i < 4; i++)
            #pragma unroll
            for (int j = 0; j < 2; j++)
                wmma::mma_sync(acc[i][j], af[i], bf[j], acc[i][j]);
    }
    #pragma unroll
    for (int i = 0; i < 4; i++)
        #pragma unroll
        for (int j = 0; j < 2; j++)
            wmma::store_matrix_sync(g_act + (size_t)(mBase + i * 16) * NPJ + nBase + j * 16,
                                    acc[i][j], NPJ, wmma::mem_row_major);
}

// ------------------------- K3: softmax over the 16 neighbors -------------------------
__global__ void k3_softmax() {
    int idx = blockIdx.x * blockDim.x + threadIdx.x;
    if (idx >= ACT_ROWS * V) return;
    float4* g = (float4*)(g_act + (size_t)idx * NB);
    float v[16];
    #pragma unroll
    for (int q = 0; q < 4; q++) {
        float4 t = g[q];
        v[q * 4 + 0] = t.x; v[q * 4 + 1] = t.y; v[q * 4 + 2] = t.z; v[q * 4 + 3] = t.w;
    }
    float mx = v[0];
    #pragma unroll
    for (int j = 1; j < 16; j++) mx = fmaxf(mx, v[j]);
    float s = 0.f;
    #pragma unroll
    for (int j = 0; j < 16; j++) { v[j] = __expf(v[j] - mx); s += v[j]; }
    float inv = 1.f / s;
    #pragma unroll
    for (int q = 0; q < 4; q++) {
        float4 t = make_float4(v[q*4] * inv, v[q*4+1] * inv, v[q*4+2] * inv, v[q*4+3] * inv);
        g[q] = t;
    }
}

// ------------------------- K4a: nfm[(k,r)][ci][p] (fp16) = sum_j act*cross ------------
__global__ void k4a_nfm() {
    int k = blockIdx.y;                    // 0..11
    int tid = threadIdx.x;                 // 512
    int pl = tid & 127, cg = tid >> 7;     // 128 p-lanes, 4 ci-lanes
    int p = blockIdx.x * 128 + pl;
    for (int ci = cg; ci < CI; ci += 4) {
        int c = ci / 6, h = c >> 2;
        const float4* xb = (const float4*)(g_cross + (size_t)ci * NPJ + p * NB);
        float4 x0 = xb[0], x1 = xb[1], x2 = xb[2], x3 = xb[3];
        int abase = (h * 12 + k) * 12;
        #pragma unroll
        for (int r = 0; r < 12; r++) {
            const float4* ar = (const float4*)(g_act + (size_t)(abase + r) * NPJ + p * NB);
            float4 a0 = ar[0], a1 = ar[1], a2 = ar[2], a3 = ar[3];
            float acc = a0.x*x0.x + a0.y*x0.y + a0.z*x0.z + a0.w*x0.w
                      + a1.x*x1.x + a1.y*x1.y + a1.z*x1.z + a1.w*x1.w
                      + a2.x*x2.x + a2.y*x2.y + a2.z*x2.z + a2.w*x2.w
                      + a3.x*x3.x + a3.y*x3.y + a3.z*x3.z + a3.w*x3.w;
            g_nfmh[((size_t)(k * 12 + r) * CI + ci) * V + p] = __float2half_rn(acc);
        }
    }
}

// ------------------------- K4b: feat via wmma, per (k,r): (64 x 2048 x 192) -----------
// grid (V/256, 144), 8 warps; warp = rows 0..63 x 32 cols.
__global__ void k4b_wmma() {
    int kr = blockIdx.y;
    int wid = threadIdx.x >> 5;
    int nBase = blockIdx.x * 256 + wid * 32;
    const __half* A = g_Wfh + (size_t)kr * DO * CI;    // 64 x 192
    const __half* B = g_nfmh + (size_t)kr * CI * V;    // 192 x 2048
    float* C = g_feat + (size_t)kr * DO * V;           // 64 x 2048
    wmma::fragment<wmma::accumulator, 16, 16, 16, float> acc[4][2];
    #pragma unroll
    for (int i = 0; i < 4; i++)
        #pragma unroll
        for (int j = 0; j < 2; j++) wmma::fill_fragment(acc[i][j], 0.0f);
    for (int k = 0; k < CI; k += 16) {
        wmma::fragment<wmma::matrix_a, 16, 16, 16, __half, wmma::row_major> af[4];
        wmma::fragment<wmma::matrix_b, 16, 16, 16, __half, wmma::row_major> bf[2];
        #pragma unroll
        for (int i = 0; i < 4; i++)
            wmma::load_matrix_sync(af[i], A + (size_t)(i * 16) * CI + k, CI);
        #pragma unroll
        for (int j = 0; j < 2; j++)
            wmma::load_matrix_sync(bf[j], B + (size_t)k * V + nBase + j * 16, V);
        #pragma unroll
        for (int i = 0; i < 4; i++)
            #pragma unroll
            for (int j = 0; j < 2; j++)
                wmma::mma_sync(acc[i][j], af[i], bf[j], acc[i][j]);
    }
    #pragma unroll
    for (int i = 0; i < 4; i++)
        #pragma unroll
        for (int j = 0; j < 2; j++)
            wmma::store_matrix_sync(C + (size_t)(i * 16) * V + nBase + j * 16,
                                    acc[i][j], V, wmma::mem_row_major);
}

// ------------------------- K5: center + k-sum + color-pair max + fm copy ----------------
__global__ void k5_final(const float* __restrict__ fm, float* __restrict__ out) {
    int idx = blockIdx.x * blockDim.x + threadIdx.x;
    const int NKA = DO * V;                // 131072
    if (idx < NKA) {
        int d = idx / V, p = idx % V;
        float ka[12];
        #pragma unroll
        for (int r = 0; r < 12; r++) ka[r] = 0.f;
        for (int ci = 0; ci < CI; ci++) {
            float x = g_fmT[ci * V + p];
            #pragma unroll
            for (int r = 0; r < 12; r++)
                ka[r] += g_Wc[(r * DO + d) * CI + ci] * x;
        }
        #pragma unroll
        for (int k = 0; k < 12; k++)
            #pragma unroll
            for (int r = 0; r < 12; r++)
                ka[r] += g_feat[((size_t)(k * 12 + r) * DO + d) * V + p];
        #pragma unroll
        for (int cc = 0; cc < 6; cc++)
            out[d * (V * 6) + p * 6 + cc] = fmaxf(ka[c_C2V[cc][0]], ka[c_C2V[cc][1]]);
    } else {
        int j = idx - NKA;
        if (j < DI * V * 6)
            out[DO * V * 6 + j] = fm[j];
    }
}

// ------------------------- launch -------------------------
extern "C" void kernel_launch(void* const* d_in, const int* in_sizes, int n_in,
                              void* d_out, int out_size) {
    const int*   nbr   = (const int*)d_in[0];
    const float* verts = (const float*)d_in[1];
    const float* fm    = (const float*)d_in[2];
    const float* Wdim  = (const float*)d_in[3];
    const float* W     = (const float*)d_in[4];
    const float* Wdir  = (const float*)d_in[5];
    float* out = (float*)d_out;

    k0_weights<<<512, 256>>>(W, Wdir, fm);
    k1_cross<<<V, 192>>>(nbr, verts, fm, Wdim);
    k2_wmma<<<dim3(NPJ / 128, ACT_ROWS / 128), 256>>>();
    k3_softmax<<<(ACT_ROWS * V + 255) / 256, 256>>>();
    k4a_nfm<<<dim3(V / 128, 12), 512>>>();
    k4b_wmma<<<dim3(V / 256, 144), 256>>>();
    k5_final<<<(DO * V + DI * V * 6 + 255) / 256, 256>>>(fm, out);
}

// round 7
// speedup vs baseline: 1.6257x; 1.3870x over previous
#include <cuda_runtime.h>
#include <cuda_fp16.h>
#include <mma.h>
#include <cstdint>

using namespace nvcuda;

// Problem dims (fixed instance)
#define V    2048
#define NB   16
#define DI   32
#define DO   64
#define NH   8
#define NPJ  (V*NB)           // 32768
#define ACT_ROWS (NH*12*12)   // 1152
#define CI   (DI*6)           // 192

// ------------------------- device scratch -------------------------
__device__ __align__(16) __half g_crossh[CI*NPJ];    // fp16 cross [ci][n]      13 MB
__device__ __align__(16) __half g_acth[ACT_ROWS*NPJ];// softmaxed act fp16      75 MB
__device__ __align__(16) __half g_nfmh[144*CI*V];    // [(k,r)][ci][p] fp16    113 MB
__device__ __align__(16) float  g_ka[12*DO*V];       // [r][d][p] fp32           6 MB
__device__ __align__(16) __half g_Mh[ACT_ROWS*CI];   // act weights fp16 (pre-scaled 0.5)
__device__ __align__(16) __half g_Wfh[144*DO*CI];    // feat weights per (k,r) fp16
__device__ __align__(16) __half g_Wch[12*DO*CI];     // center weights per r fp16
__device__ __align__(16) __half g_fmTh[CI*V];        // fm transposed [ci][p] fp16

// ------------------------- constants -------------------------
__constant__ float c_VS[12][3] = {
 {0.f, 0.5257311121f, 0.8506508084f},
 {0.f, 0.5257311121f,-0.8506508084f},
 {0.f,-0.5257311121f, 0.8506508084f},
 {0.f,-0.5257311121f,-0.8506508084f},
 { 0.5257311121f, 0.8506508084f,0.f},
 { 0.5257311121f,-0.8506508084f,0.f},
 {-0.5257311121f, 0.8506508084f,0.f},
 {-0.5257311121f,-0.8506508084f,0.f},
 { 0.8506508084f,0.f, 0.5257311121f},
 { 0.8506508084f,0.f,-0.5257311121f},
 {-0.8506508084f,0.f, 0.5257311121f},
 {-0.8506508084f,0.f,-0.5257311121f}};

__constant__ int c_C2V[6][2] = {{0,1},{6,7},{2,11},{4,9},{5,8},{3,10}};

__constant__ int c_INV[12][6] = {
 {0,1,2,3,4,5},{0,5,4,3,2,1},{4,3,0,5,2,1},{1,2,4,3,5,0},
 {3,5,2,0,4,1},{1,4,3,5,0,2},{4,0,3,1,2,5},{1,0,2,4,3,5},
 {4,1,2,5,0,3},{3,1,4,0,2,5},{2,1,4,5,3,0},{4,5,0,3,1,2}};

__constant__ int c_ROLL[5][6] = {
 {0,1,2,3,4,5},{0,2,3,4,5,1},{0,3,4,5,1,2},{0,4,5,1,2,3},{0,5,1,2,3,4}};

__device__ __forceinline__ float w13(const float* __restrict__ Wp, int k, int m) {
    if (k == 0)  return (m == 0) ? Wp[0] : Wp[1];
    if (k == 1)  return (m == 0) ? Wp[2] : Wp[3];
    if (k == 12) return (m == 0) ? Wp[4] : Wp[5];
    int pp = (k - 2) / 5, s = (k - 2) % 5;
    return Wp[6 + pp * 6 + c_ROLL[s][m]];
}

// ------------------------- K0: weight expansion + fm transpose -------------------------
__global__ void k0_weights(const float* __restrict__ W, const float* __restrict__ Wdir,
                           const float* __restrict__ fm) {
    const int N1 = ACT_ROWS * CI;          // 221184
    const int N2 = 144 * DO * CI;          // 1769472
    const int N3 = 12 * DO * CI;           // 147456
    const int N4 = CI * V;                 // 393216
    const int total = N1 + N2 + N3 + N4;
    for (int idx = blockIdx.x * blockDim.x + threadIdx.x; idx < total;
         idx += gridDim.x * blockDim.x) {
        if (idx < N1) {
            int ci = idx % CI, row = idx / CI;
            int r = row % 12, hk = row / 12, k = hk % 12, h = hk / 12;
            int c = ci / 6, i = ci % 6;
            // fold the 1/sqrt(dph)=0.5 logit scale into the weights
            g_Mh[idx] = __float2half_rn(0.5f * w13(Wdir + (h * DI + c) * 18, k, c_INV[r][i]));
        } else if (idx < N1 + N2) {
            int j = idx - N1;
            int ci = j % CI, dj = j / CI, d = dj % DO, kr = dj / DO;
            int r = kr % 12, k = kr / 12;
            g_Wfh[j] = __float2half_rn(w13(W + (d * DI + ci / 6) * 18, k, c_INV[r][ci % 6]));
        } else if (idx < N1 + N2 + N3) {
            int j = idx - N1 - N2;
            int ci = j % CI, dj = j / CI, d = dj % DO, r = dj / DO;
            g_Wch[j] = __float2half_rn(w13(W + (d * DI + ci / 6) * 18, 12, c_INV[r][ci % 6]));
        } else {
            int j = idx - N1 - N2 - N3;
            int p = j % V, ci = j / V;
            g_fmTh[j] = __float2half_rn(fm[((ci / 6) * V + p) * 6 + (ci % 6)]);
        }
    }
}

// ------------------------- K1: per-vertex cross features -------------------------
__global__ void k1_cross(const int* __restrict__ nbr, const float* __restrict__ verts,
                         const float* __restrict__ fm, const float* __restrict__ Wdim) {
    int p = blockIdx.x;
    int t = threadIdx.x;   // 192 threads
    __shared__ int   s_nbr[NB];
    __shared__ float s_cin[DI + 1][NB][6];
    __shared__ float s_wd[(DI + 1) * DI];
    if (t < NB) s_nbr[t] = nbr[p * NB + t];
    for (int x = t; x < (DI + 1) * DI; x += 192) s_wd[x] = Wdim[x];
    __syncthreads();
    if (t < NB) {
        int q = s_nbr[t];
        float cx = verts[p * 3], cy = verts[p * 3 + 1], cz = verts[p * 3 + 2];
        float dx = verts[q * 3] - cx, dy = verts[q * 3 + 1] - cy, dz = verts[q * 3 + 2] - cz;
        float nrm = fmaxf(sqrtf(dx * dx + dy * dy + dz * dz), 1e-12f);
        dx /= nrm; dy /= nrm; dz /= nrm;
        float de[12];
        #pragma unroll
        for (int v = 0; v < 12; v++)
            de[v] = c_VS[v][0] * dx + c_VS[v][1] * dy + c_VS[v][2] * dz;
        #pragma unroll
        for (int i = 0; i < 6; i++)
            s_cin[DI][t][i] = fmaxf(de[c_C2V[i][0]], de[c_C2V[i][1]]);
    }
    for (int x = t; x < DI * NB * 6; x += 192) {
        int c = x / (NB * 6), rem = x % (NB * 6), j = rem / 6, i = rem % 6;
        s_cin[c][j][i] = fm[(c * V + s_nbr[j]) * 6 + i];
    }
    __syncthreads();
    int o = t / 6, i = t % 6;
    for (int j = 0; j < NB; j++) {
        float a = 0.f;
        #pragma unroll
        for (int c = 0; c <= DI; c++) a += s_wd[c * DI + o] * s_cin[c][j][i];
        g_crossh[(size_t)(o * 6 + i) * NPJ + p * NB + j] = __float2half_rn(a);
    }
}

// ------------------------- K2: act logits GEMM + fused softmax ------------------------
// C(1152 x 32768) = Mh @ crossh. Block tile 128x128, 8 warps (2x4), warp 64x32.
// Smem-staged, double-buffered plain LDG->STS. Epilogue: per-warp C tile to smem,
// softmax over each 16-col neighbor group, write fp16 act.
__global__ __launch_bounds__(256) void k2_act() {
    extern __shared__ char dyn[];
    __half* sA = (__half*)dyn;             // [2][128][24]  (12288 B)
    __half* sB = (__half*)(dyn + 12288);   // [2][16][136]  ( 8704 B)
    float*  sC = (float*)dyn;              // [8][64][36]   (73728 B, reuse after loop)

    int m0 = blockIdx.y * 128, n0 = blockIdx.x * 128;
    int tid = threadIdx.x, lane = tid & 31, wid = tid >> 5;
    int wmL = (wid >> 2) * 64, wnL = (wid & 3) * 32;

    wmma::fragment<wmma::accumulator, 16, 16, 16, float> acc[4][2];
    #pragma unroll
    for (int i = 0; i < 4; i++)
        #pragma unroll
        for (int j = 0; j < 2; j++) wmma::fill_fragment(acc[i][j], 0.0f);

    int ar = tid >> 1, ac = (tid & 1) * 8;
    int br = tid >> 4, bc = (tid & 15) * 8;

    auto copyAB = [&](int kt, int buf) {
        int k0 = kt * 16;
        *(float4*)&sA[buf * 3072 + ar * 24 + ac] =
            *(const float4*)&g_Mh[(size_t)(m0 + ar) * CI + k0 + ac];
        *(float4*)&sB[buf * 2176 + br * 136 + bc] =
            *(const float4*)&g_crossh[(size_t)(k0 + br) * NPJ + n0 + bc];
    };

    copyAB(0, 0);
    __syncthreads();
    for (int kt = 0; kt < 12; kt++) {
        int buf = kt & 1;
        if (kt + 1 < 12) copyAB(kt + 1, buf ^ 1);
        wmma::fragment<wmma::matrix_a, 16, 16, 16, __half, wmma::row_major> af[4];
        wmma::fragment<wmma::matrix_b, 16, 16, 16, __half, wmma::row_major> bf[2];
        #pragma unroll
        for (int i = 0; i < 4; i++)
            wmma::load_matrix_sync(af[i], &sA[buf * 3072 + (wmL + i * 16) * 24], 24);
        #pragma unroll
        for (int j = 0; j < 2; j++)
            wmma::load_matrix_sync(bf[j], &sB[buf * 2176 + wnL + j * 16], 136);
        #pragma unroll
        for (int i = 0; i < 4; i++)
            #pragma unroll
            for (int j = 0; j < 2; j++)
                wmma::mma_sync(acc[i][j], af[i], bf[j], acc[i][j]);
        __syncthreads();
    }

    // --- fused softmax epilogue ---
    float* sCw = sC + wid * 64 * 36;       // per-warp 64x36 tile
    #pragma unroll
    for (int i = 0; i < 4; i++)
        #pragma unroll
        for (int j = 0; j < 2; j++)
            wmma::store_matrix_sync(&sCw[(i * 16) * 36 + j * 16], acc[i][j], 36,
                                    wmma::mem_row_major);
    __syncwarp();
    #pragma unroll
    for (int it = 0; it < 4; it++) {
        int g = lane + it * 32;            // 0..127 groups: 64 rows x 2 halves
        int row = g >> 1, half = g & 1;
        const float* src = &sCw[row * 36 + half * 16];
        float v[16];
        #pragma unroll
        for (int q = 0; q < 16; q++) v[q] = src[q];
        float mx = v[0];
        #pragma unroll
        for (int q = 1; q < 16; q++) mx = fmaxf(mx, v[q]);
        float s = 0.f;
        #pragma unroll
        for (int q = 0; q < 16; q++) { v[q] = __expf(v[q] - mx); s += v[q]; }
        float inv = 1.f / s;
        __align__(16) __half hv[16];
        #pragma unroll
        for (int q = 0; q < 16; q++) hv[q] = __float2half_rn(v[q] * inv);
        size_t off = (size_t)(m0 + wmL + row) * NPJ + n0 + wnL + half * 16;
        *(uint4*)&g_acth[off]     = *(uint4*)&hv[0];
        *(uint4*)&g_acth[off + 8] = *(uint4*)&hv[8];
    }
}

// ------------------------- K4a: nfm[(k,r)][ci][p] (fp16) = sum_j act*cross ------------
__global__ void k4a_nfm() {
    int k = blockIdx.y;                    // 0..11
    int tid = threadIdx.x;                 // 512
    int pl = tid & 127, cg = tid >> 7;     // 128 p-lanes, 4 ci-lanes
    int p = blockIdx.x * 128 + pl;
    for (int ci = cg; ci < CI; ci += 4) {
        int c = ci / 6, h = c >> 2;
        // 16 neighbors = 16 halfs = 32 bytes = TWO uint4 loads
        size_t xbase = (size_t)ci * NPJ + p * NB;
        uint4 x0 = *(const uint4*)&g_crossh[xbase];
        uint4 x1 = *(const uint4*)&g_crossh[xbase + 8];
        float2 xv[8];
        {
            const __half2* h0 = (const __half2*)&x0;
            const __half2* h1 = (const __half2*)&x1;
            #pragma unroll
            for (int q = 0; q < 4; q++) { xv[q] = __half22float2(h0[q]); xv[q + 4] = __half22float2(h1[q]); }
        }
        int abase = (h * 12 + k) * 12;
        #pragma unroll
        for (int r = 0; r < 12; r++) {
            size_t aoff = (size_t)(abase + r) * NPJ + p * NB;
            uint4 a0 = *(const uint4*)&g_acth[aoff];
            uint4 a1 = *(const uint4*)&g_acth[aoff + 8];
            const __half2* ah0 = (const __half2*)&a0;
            const __half2* ah1 = (const __half2*)&a1;
            float acc = 0.f;
            #pragma unroll
            for (int q = 0; q < 4; q++) {
                float2 av = __half22float2(ah0[q]);
                acc += av.x * xv[q].x + av.y * xv[q].y;
            }
            #pragma unroll
            for (int q = 0; q < 4; q++) {
                float2 av = __half22float2(ah1[q]);
                acc += av.x * xv[q + 4].x + av.y * xv[q + 4].y;
            }
            g_nfmh[((size_t)(k * 12 + r) * CI + ci) * V + p] = __float2half_rn(acc);
        }
    }
}

// ------------------------- K4b: ka[r] = sum over 13 slabs of W_slab @ B_slab ----------
// Per r: 12 x (Wf(k,r) 64x192 @ nfm(k,r) 192x2048) + Wc(r) @ fmT. Accum fp32 -> g_ka.
// grid (16, 12), 128 threads = 4 warps; block tile 64 x 128, warp 64 x 32.
__global__ __launch_bounds__(128) void k4b_ka() {
    __shared__ __align__(16) __half sA[2][64][24];
    __shared__ __align__(16) __half sB[2][16][136];
    int r = blockIdx.y;
    int n0 = blockIdx.x * 128;
    int tid = threadIdx.x, wid = tid >> 5;
    int wn = wid * 32;

    wmma::fragment<wmma::accumulator, 16, 16, 16, float> acc[4][2];
    #pragma unroll
    for (int i = 0; i < 4; i++)
        #pragma unroll
        for (int j = 0; j < 2; j++) wmma::fill_fragment(acc[i][j], 0.0f);

    auto aPtr = [&](int s) -> const __half* {
        return (s < 12) ? g_Wfh + (size_t)(s * 12 + r) * DO * CI
                        : g_Wch + (size_t)r * DO * CI;
    };
    auto bPtr = [&](int s) -> const __half* {
        return (s < 12) ? g_nfmh + (size_t)(s * 12 + r) * CI * V
                        : g_fmTh;
    };

    int arow = tid >> 1, acol = (tid & 1) * 8;
    auto copyAB = [&](int it, int buf) {
        int s = it / 12, k0 = (it % 12) * 16;
        const __half* A = aPtr(s);
        const __half* B = bPtr(s);
        *(float4*)&sA[buf][arow][acol] = *(const float4*)&A[(size_t)arow * CI + k0 + acol];
        #pragma unroll
        for (int q = 0; q < 2; q++) {
            int li = tid + q * 128;
            int brow = li >> 4, bcol = (li & 15) * 8;
            *(float4*)&sB[buf][brow][bcol] = *(const float4*)&B[(size_t)(k0 + brow) * V + n0 + bcol];
        }
    };

    const int NIT = 13 * 12;   // 156
    copyAB(0, 0);
    __syncthreads();
    for (int it = 0; it < NIT; it++) {
        int buf = it & 1;
        if (it + 1 < NIT) copyAB(it + 1, buf ^ 1);
        wmma::fragment<wmma::matrix_a, 16, 16, 16, __half, wmma::row_major> af[4];
        wmma::fragment<wmma::matrix_b, 16, 16, 16, __half, wmma::row_major> bf[2];
        #pragma unroll
        for (int i = 0; i < 4; i++)
            wmma::load_matrix_sync(af[i], &sA[buf][i * 16][0], 24);
        #pragma unroll
        for (int j = 0; j < 2; j++)
            wmma::load_matrix_sync(bf[j], &sB[buf][0][wn + j * 16], 136);
        #pragma unroll
        for (int i = 0; i < 4; i++)
            #pragma unroll
            for (int j = 0; j < 2; j++)
                wmma::mma_sync(acc[i][j], af[i], bf[j], acc[i][j]);
        __syncthreads();
    }
    #pragma unroll
    for (int i = 0; i < 4; i++)
        #pragma unroll
        for (int j = 0; j < 2; j++)
            wmma::store_matrix_sync(g_ka + ((size_t)r * DO + i * 16) * V + n0 + wn + j * 16,
                                    acc[i][j], V, wmma::mem_row_major);
}

// ------------------------- K5: color-pair max + fm copy ----------------
__global__ void k5_final(const float* __restrict__ fm, float* __restrict__ out) {
    int idx = blockIdx.x * blockDim.x + threadIdx.x;
    const int NKA = DO * V;                // 131072
    if (idx < NKA) {
        int d = idx / V, p = idx % V;
        float ka[12];
        #pragma unroll
        for (int r = 0; r < 12; r++) ka[r] = g_ka[(size_t)(r * DO + d) * V + p];
        #pragma unroll
        for (int cc = 0; cc < 6; cc++)
            out[d * (V * 6) + p * 6 + cc] = fmaxf(ka[c_C2V[cc][0]], ka[c_C2V[cc][1]]);
    } else {
        int j = idx - NKA;
        if (j < DI * V * 6)
            out[DO * V * 6 + j] = fm[j];
    }
}

// ------------------------- launch -------------------------
extern "C" void kernel_launch(void* const* d_in, const int* in_sizes, int n_in,
                              void* d_out, int out_size) {
    const int*   nbr   = (const int*)d_in[0];
    const float* verts = (const float*)d_in[1];
    const float* fm    = (const float*)d_in[2];
    const float* Wdim  = (const float*)d_in[3];
    const float* W     = (const float*)d_in[4];
    const float* Wdir  = (const float*)d_in[5];
    float* out = (float*)d_out;

    const int K2_SMEM = 8 * 64 * 36 * 4;   // 73728 B (sC; covers sA+sB too)
    cudaFuncSetAttribute(k2_act, cudaFuncAttributeMaxDynamicSharedMemorySize, K2_SMEM);

    k0_weights<<<512, 256>>>(W, Wdir, fm);
    k1_cross<<<V, 192>>>(nbr, verts, fm, Wdim);
    k2_act<<<dim3(NPJ / 128, ACT_ROWS / 128), 256, K2_SMEM>>>();
    k4a_nfm<<<dim3(V / 128, 12), 512>>>();
    k4b_ka<<<dim3(V / 128, 12), 128>>>();
    k5_final<<<(DO * V + DI * V * 6 + 255) / 256, 256>>>(fm, out);
}

// round 8
// speedup vs baseline: 3.1184x; 1.9182x over previous
#include <cuda_runtime.h>
#include <cuda_fp16.h>
#include <mma.h>
#include <cstdint>

using namespace nvcuda;

// Problem dims (fixed instance)
#define V    2048
#define NB   16
#define DI   32
#define DO   64
#define NH   8
#define NPJ  (V*NB)           // 32768
#define ACT_ROWS (NH*12*12)   // 1152
#define CI   (DI*6)           // 192

// ------------------------- device scratch -------------------------
__device__ __align__(16) __half g_crossh[CI*NPJ];    // fp16 cross [ci][n]      13 MB
__device__ __align__(16) __half g_acth[ACT_ROWS*NPJ];// softmaxed act fp16      75 MB
__device__ __align__(16) __half g_nfmh[144*CI*V];    // [(k,r)][ci][p] fp16    113 MB
__device__ __align__(16) float  g_ka[12*DO*V];       // [r][d][p] fp32           6 MB
__device__ __align__(16) __half g_Mh[ACT_ROWS*CI];   // act weights fp16 (pre-scaled 0.5)
__device__ __align__(16) __half g_Wfh[144*DO*CI];    // feat weights per (k,r) fp16
__device__ __align__(16) __half g_Wch[12*DO*CI];     // center weights per r fp16
__device__ __align__(16) __half g_fmTh[CI*V];        // fm transposed [ci][p] fp16

// ------------------------- constants -------------------------
__constant__ float c_VS[12][3] = {
 {0.f, 0.5257311121f, 0.8506508084f},
 {0.f, 0.5257311121f,-0.8506508084f},
 {0.f,-0.5257311121f, 0.8506508084f},
 {0.f,-0.5257311121f,-0.8506508084f},
 { 0.5257311121f, 0.8506508084f,0.f},
 { 0.5257311121f,-0.8506508084f,0.f},
 {-0.5257311121f, 0.8506508084f,0.f},
 {-0.5257311121f,-0.8506508084f,0.f},
 { 0.8506508084f,0.f, 0.5257311121f},
 { 0.8506508084f,0.f,-0.5257311121f},
 {-0.8506508084f,0.f, 0.5257311121f},
 {-0.8506508084f,0.f,-0.5257311121f}};

__constant__ int c_C2V[6][2] = {{0,1},{6,7},{2,11},{4,9},{5,8},{3,10}};

__constant__ int c_INV[12][6] = {
 {0,1,2,3,4,5},{0,5,4,3,2,1},{4,3,0,5,2,1},{1,2,4,3,5,0},
 {3,5,2,0,4,1},{1,4,3,5,0,2},{4,0,3,1,2,5},{1,0,2,4,3,5},
 {4,1,2,5,0,3},{3,1,4,0,2,5},{2,1,4,5,3,0},{4,5,0,3,1,2}};

__constant__ int c_ROLL[5][6] = {
 {0,1,2,3,4,5},{0,2,3,4,5,1},{0,3,4,5,1,2},{0,4,5,1,2,3},{0,5,1,2,3,4}};

__device__ __forceinline__ float w13(const float* __restrict__ Wp, int k, int m) {
    if (k == 0)  return (m == 0) ? Wp[0] : Wp[1];
    if (k == 1)  return (m == 0) ? Wp[2] : Wp[3];
    if (k == 12) return (m == 0) ? Wp[4] : Wp[5];
    int pp = (k - 2) / 5, s = (k - 2) % 5;
    return Wp[6 + pp * 6 + c_ROLL[s][m]];
}

// ------------------------- K0: weight expansion + fm transpose -------------------------
__global__ void k0_weights(const float* __restrict__ W, const float* __restrict__ Wdir,
                           const float* __restrict__ fm) {
    const int N1 = ACT_ROWS * CI;          // 221184
    const int N2 = 144 * DO * CI;          // 1769472
    const int N3 = 12 * DO * CI;           // 147456
    const int N4 = CI * V;                 // 393216
    const int total = N1 + N2 + N3 + N4;
    for (int idx = blockIdx.x * blockDim.x + threadIdx.x; idx < total;
         idx += gridDim.x * blockDim.x) {
        if (idx < N1) {
            int ci = idx % CI, row = idx / CI;
            int r = row % 12, hk = row / 12, k = hk % 12, h = hk / 12;
            int c = ci / 6, i = ci % 6;
            // fold the 1/sqrt(dph)=0.5 logit scale into the weights
            g_Mh[idx] = __float2half_rn(0.5f * w13(Wdir + (h * DI + c) * 18, k, c_INV[r][i]));
        } else if (idx < N1 + N2) {
            int j = idx - N1;
            int ci = j % CI, dj = j / CI, d = dj % DO, kr = dj / DO;
            int r = kr % 12, k = kr / 12;
            g_Wfh[j] = __float2half_rn(w13(W + (d * DI + ci / 6) * 18, k, c_INV[r][ci % 6]));
        } else if (idx < N1 + N2 + N3) {
            int j = idx - N1 - N2;
            int ci = j % CI, dj = j / CI, d = dj % DO, r = dj / DO;
            g_Wch[j] = __float2half_rn(w13(W + (d * DI + ci / 6) * 18, 12, c_INV[r][ci % 6]));
        } else {
            int j = idx - N1 - N2 - N3;
            int p = j % V, ci = j / V;
            g_fmTh[j] = __float2half_rn(fm[((ci / 6) * V + p) * 6 + (ci % 6)]);
        }
    }
}

// ------------------------- K1: per-vertex cross features -------------------------
__global__ void k1_cross(const int* __restrict__ nbr, const float* __restrict__ verts,
                         const float* __restrict__ fm, const float* __restrict__ Wdim) {
    int p = blockIdx.x;
    int t = threadIdx.x;   // 192 threads
    __shared__ int   s_nbr[NB];
    __shared__ float s_cin[DI + 1][NB][6];
    __shared__ float s_wd[(DI + 1) * DI];
    if (t < NB) s_nbr[t] = nbr[p * NB + t];
    for (int x = t; x < (DI + 1) * DI; x += 192) s_wd[x] = Wdim[x];
    __syncthreads();
    if (t < NB) {
        int q = s_nbr[t];
        float cx = verts[p * 3], cy = verts[p * 3 + 1], cz = verts[p * 3 + 2];
        float dx = verts[q * 3] - cx, dy = verts[q * 3 + 1] - cy, dz = verts[q * 3 + 2] - cz;
        float nrm = fmaxf(sqrtf(dx * dx + dy * dy + dz * dz), 1e-12f);
        dx /= nrm; dy /= nrm; dz /= nrm;
        float de[12];
        #pragma unroll
        for (int v = 0; v < 12; v++)
            de[v] = c_VS[v][0] * dx + c_VS[v][1] * dy + c_VS[v][2] * dz;
        #pragma unroll
        for (int i = 0; i < 6; i++)
            s_cin[DI][t][i] = fmaxf(de[c_C2V[i][0]], de[c_C2V[i][1]]);
    }
    for (int x = t; x < DI * NB * 6; x += 192) {
        int c = x / (NB * 6), rem = x % (NB * 6), j = rem / 6, i = rem % 6;
        s_cin[c][j][i] = fm[(c * V + s_nbr[j]) * 6 + i];
    }
    __syncthreads();
    int o = t / 6, i = t % 6;
    for (int j = 0; j < NB; j++) {
        float a = 0.f;
        #pragma unroll
        for (int c = 0; c <= DI; c++) a += s_wd[c * DI + o] * s_cin[c][j][i];
        g_crossh[(size_t)(o * 6 + i) * NPJ + p * NB + j] = __float2half_rn(a);
    }
}

// ------------------------- K2: act logits GEMM + fused softmax ------------------------
// C(1152 x 32768) = Mh @ crossh. Block tile 128x128, 8 warps (2x4), warp 64x32.
// Smem-staged, double-buffered plain LDG->STS. Epilogue: per-warp C tile to smem,
// softmax over each 16-col neighbor group, write fp16 act.
__global__ __launch_bounds__(256) void k2_act() {
    extern __shared__ char dyn[];
    __half* sA = (__half*)dyn;             // [2][128][24]  (12288 B)
    __half* sB = (__half*)(dyn + 12288);   // [2][16][136]  ( 8704 B)
    float*  sC = (float*)dyn;              // [8][64][36]   (73728 B, reuse after loop)

    int m0 = blockIdx.y * 128, n0 = blockIdx.x * 128;
    int tid = threadIdx.x, lane = tid & 31, wid = tid >> 5;
    int wmL = (wid >> 2) * 64, wnL = (wid & 3) * 32;

    wmma::fragment<wmma::accumulator, 16, 16, 16, float> acc[4][2];
    #pragma unroll
    for (int i = 0; i < 4; i++)
        #pragma unroll
        for (int j = 0; j < 2; j++) wmma::fill_fragment(acc[i][j], 0.0f);

    int ar = tid >> 1, ac = (tid & 1) * 8;
    int br = tid >> 4, bc = (tid & 15) * 8;

    auto copyAB = [&](int kt, int buf) {
        int k0 = kt * 16;
        *(float4*)&sA[buf * 3072 + ar * 24 + ac] =
            *(const float4*)&g_Mh[(size_t)(m0 + ar) * CI + k0 + ac];
        *(float4*)&sB[buf * 2176 + br * 136 + bc] =
            *(const float4*)&g_crossh[(size_t)(k0 + br) * NPJ + n0 + bc];
    };

    copyAB(0, 0);
    __syncthreads();
    for (int kt = 0; kt < 12; kt++) {
        int buf = kt & 1;
        if (kt + 1 < 12) copyAB(kt + 1, buf ^ 1);
        wmma::fragment<wmma::matrix_a, 16, 16, 16, __half, wmma::row_major> af[4];
        wmma::fragment<wmma::matrix_b, 16, 16, 16, __half, wmma::row_major> bf[2];
        #pragma unroll
        for (int i = 0; i < 4; i++)
            wmma::load_matrix_sync(af[i], &sA[buf * 3072 + (wmL + i * 16) * 24], 24);
        #pragma unroll
        for (int j = 0; j < 2; j++)
            wmma::load_matrix_sync(bf[j], &sB[buf * 2176 + wnL + j * 16], 136);
        #pragma unroll
        for (int i = 0; i < 4; i++)
            #pragma unroll
            for (int j = 0; j < 2; j++)
                wmma::mma_sync(acc[i][j], af[i], bf[j], acc[i][j]);
        __syncthreads();
    }

    // --- fused softmax epilogue ---
    float* sCw = sC + wid * 64 * 36;       // per-warp 64x36 tile
    #pragma unroll
    for (int i = 0; i < 4; i++)
        #pragma unroll
        for (int j = 0; j < 2; j++)
            wmma::store_matrix_sync(&sCw[(i * 16) * 36 + j * 16], acc[i][j], 36,
                                    wmma::mem_row_major);
    __syncwarp();
    #pragma unroll
    for (int it = 0; it < 4; it++) {
        int g = lane + it * 32;            // 0..127 groups: 64 rows x 2 halves
        int row = g >> 1, half = g & 1;
        const float* src = &sCw[row * 36 + half * 16];
        float v[16];
        #pragma unroll
        for (int q = 0; q < 16; q++) v[q] = src[q];
        float mx = v[0];
        #pragma unroll
        for (int q = 1; q < 16; q++) mx = fmaxf(mx, v[q]);
        float s = 0.f;
        #pragma unroll
        for (int q = 0; q < 16; q++) { v[q] = __expf(v[q] - mx); s += v[q]; }
        float inv = 1.f / s;
        __align__(16) __half hv[16];
        #pragma unroll
        for (int q = 0; q < 16; q++) hv[q] = __float2half_rn(v[q] * inv);
        size_t off = (size_t)(m0 + wmL + row) * NPJ + n0 + wnL + half * 16;
        *(uint4*)&g_acth[off]     = *(uint4*)&hv[0];
        *(uint4*)&g_acth[off + 8] = *(uint4*)&hv[8];
    }
}

// ------------------------- K4a: nfm[(k,r)][ci][p] (fp16) = sum_j act*cross ------------
// grid (V/128, 12, 4): z splits the ci range into 4 chunks of 48 -> 768 CTAs.
__global__ void k4a_nfm() {
    int k = blockIdx.y;                    // 0..11
    int z = blockIdx.z;                    // 0..3 (ci chunk)
    int tid = threadIdx.x;                 // 512
    int pl = tid & 127, cg = tid >> 7;     // 128 p-lanes, 4 ci-lanes
    int p = blockIdx.x * 128 + pl;
    #pragma unroll
    for (int i = 0; i < 12; i++) {
        int ci = z * 48 + i * 4 + cg;
        int c = ci / 6, h = c >> 2;
        // 16 neighbors = 16 halfs = 32 bytes = TWO uint4 loads
        size_t xbase = (size_t)ci * NPJ + p * NB;
        uint4 x0 = *(const uint4*)&g_crossh[xbase];
        uint4 x1 = *(const uint4*)&g_crossh[xbase + 8];
        float2 xv[8];
        {
            const __half2* h0 = (const __half2*)&x0;
            const __half2* h1 = (const __half2*)&x1;
            #pragma unroll
            for (int q = 0; q < 4; q++) { xv[q] = __half22float2(h0[q]); xv[q + 4] = __half22float2(h1[q]); }
        }
        int abase = (h * 12 + k) * 12;
        #pragma unroll
        for (int r = 0; r < 12; r++) {
            size_t aoff = (size_t)(abase + r) * NPJ + p * NB;
            uint4 a0 = *(const uint4*)&g_acth[aoff];
            uint4 a1 = *(const uint4*)&g_acth[aoff + 8];
            const __half2* ah0 = (const __half2*)&a0;
            const __half2* ah1 = (const __half2*)&a1;
            float acc = 0.f;
            #pragma unroll
            for (int q = 0; q < 4; q++) {
                float2 av = __half22float2(ah0[q]);
                acc += av.x * xv[q].x + av.y * xv[q].y;
            }
            #pragma unroll
            for (int q = 0; q < 4; q++) {
                float2 av = __half22float2(ah1[q]);
                acc += av.x * xv[q + 4].x + av.y * xv[q + 4].y;
            }
            g_nfmh[((size_t)(k * 12 + r) * CI + ci) * V + p] = __float2half_rn(acc);
        }
    }
}

// ------------------------- K4b: ka[r] = sum over 13 slabs of W_slab @ B_slab ----------
// Per r: 12 x (Wf(k,r) 64x192 @ nfm(k,r) 192x2048) + Wc(r) @ fmT. Accum fp32 -> g_ka.
// grid (32, 12) = 384 CTAs, 128 threads = 4 warps; block tile 64 x 64, warp 64 x 16.
__global__ __launch_bounds__(128) void k4b_ka() {
    __shared__ __align__(16) __half sA[2][64][24];
    __shared__ __align__(16) __half sB[2][16][72];
    int r = blockIdx.y;
    int n0 = blockIdx.x * 64;
    int tid = threadIdx.x, wid = tid >> 5;
    int wn = wid * 16;

    wmma::fragment<wmma::accumulator, 16, 16, 16, float> acc[4];
    #pragma unroll
    for (int i = 0; i < 4; i++) wmma::fill_fragment(acc[i], 0.0f);

    auto aPtr = [&](int s) -> const __half* {
        return (s < 12) ? g_Wfh + (size_t)(s * 12 + r) * DO * CI
                        : g_Wch + (size_t)r * DO * CI;
    };
    auto bPtr = [&](int s) -> const __half* {
        return (s < 12) ? g_nfmh + (size_t)(s * 12 + r) * CI * V
                        : g_fmTh;
    };

    int arow = tid >> 1, acol = (tid & 1) * 8;
    int brow = tid >> 3, bcol = (tid & 7) * 8;
    auto copyAB = [&](int it, int buf) {
        int s = it / 12, k0 = (it % 12) * 16;
        const __half* A = aPtr(s);
        const __half* B = bPtr(s);
        *(float4*)&sA[buf][arow][acol] = *(const float4*)&A[(size_t)arow * CI + k0 + acol];
        *(float4*)&sB[buf][brow][bcol] = *(const float4*)&B[(size_t)(k0 + brow) * V + n0 + bcol];
    };

    const int NIT = 13 * 12;   // 156
    copyAB(0, 0);
    __syncthreads();
    for (int it = 0; it < NIT; it++) {
        int buf = it & 1;
        if (it + 1 < NIT) copyAB(it + 1, buf ^ 1);
        wmma::fragment<wmma::matrix_a, 16, 16, 16, __half, wmma::row_major> af[4];
        wmma::fragment<wmma::matrix_b, 16, 16, 16, __half, wmma::row_major> bf;
        #pragma unroll
        for (int i = 0; i < 4; i++)
            wmma::load_matrix_sync(af[i], &sA[buf][i * 16][0], 24);
        wmma::load_matrix_sync(bf, &sB[buf][0][wn], 72);
        #pragma unroll
        for (int i = 0; i < 4; i++)
            wmma::mma_sync(acc[i], af[i], bf, acc[i]);
        __syncthreads();
    }
    #pragma unroll
    for (int i = 0; i < 4; i++)
        wmma::store_matrix_sync(g_ka + ((size_t)r * DO + i * 16) * V + n0 + wn,
                                acc[i], V, wmma::mem_row_major);
}

// ------------------------- K5: color-pair max + fm copy ----------------
__global__ void k5_final(const float* __restrict__ fm, float* __restrict__ out) {
    int idx = blockIdx.x * blockDim.x + threadIdx.x;
    const int NKA = DO * V;                // 131072
    if (idx < NKA) {
        int d = idx / V, p = idx % V;
        float ka[12];
        #pragma unroll
        for (int r = 0; r < 12; r++) ka[r] = g_ka[(size_t)(r * DO + d) * V + p];
        #pragma unroll
        for (int cc = 0; cc < 6; cc++)
            out[d * (V * 6) + p * 6 + cc] = fmaxf(ka[c_C2V[cc][0]], ka[c_C2V[cc][1]]);
    } else {
        int j = idx - NKA;
        if (j < DI * V * 6)
            out[DO * V * 6 + j] = fm[j];
    }
}

// ------------------------- launch -------------------------
extern "C" void kernel_launch(void* const* d_in, const int* in_sizes, int n_in,
                              void* d_out, int out_size) {
    const int*   nbr   = (const int*)d_in[0];
    const float* verts = (const float*)d_in[1];
    const float* fm    = (const float*)d_in[2];
    const float* Wdim  = (const float*)d_in[3];
    const float* W     = (const float*)d_in[4];
    const float* Wdir  = (const float*)d_in[5];
    float* out = (float*)d_out;

    const int K2_SMEM = 8 * 64 * 36 * 4;   // 73728 B (sC; covers sA+sB too)
    cudaFuncSetAttribute(k2_act, cudaFuncAttributeMaxDynamicSharedMemorySize, K2_SMEM);

    k0_weights<<<512, 256>>>(W, Wdir, fm);
    k1_cross<<<V, 192>>>(nbr, verts, fm, Wdim);
    k2_act<<<dim3(NPJ / 128, ACT_ROWS / 128), 256, K2_SMEM>>>();
    k4a_nfm<<<dim3(V / 128, 12, 4), 512>>>();
    k4b_ka<<<dim3(V / 64, 12), 128>>>();
    k5_final<<<(DO * V + DI * V * 6 + 255) / 256, 256>>>(fm, out);
}

// round 11
// speedup vs baseline: 4.0003x; 1.2828x over previous
#include <cuda_runtime.h>
#include <cuda_fp16.h>
#include <mma.h>
#include <cstdint>

using namespace nvcuda;

// Problem dims (fixed instance)
#define V    2048
#define NB   16
#define DI   32
#define DO   64
#define NH   8
#define NPJ  (V*NB)           // 32768
#define ACT_ROWS (NH*12*12)   // 1152
#define CI   (DI*6)           // 192

// ------------------------- device scratch -------------------------
__device__ __align__(16) __half g_crossh[CI*NPJ];    // fp16 cross [ci][n]      13 MB
__device__ __align__(16) __half g_acth[ACT_ROWS*NPJ];// softmaxed act fp16      75 MB
__device__ __align__(16) __half g_nfmh[144*CI*V];    // [(k,r)][ci][p] fp16    113 MB
__device__ __align__(16) float  g_ka[12*DO*V];       // [r][d][p] fp32           6 MB
__device__ __align__(16) __half g_Mh[ACT_ROWS*CI];   // act weights fp16 (pre-scaled 0.5)
__device__ __align__(16) __half g_Wfh[144*DO*CI];    // feat weights per (k,r) fp16
__device__ __align__(16) __half g_Wch[12*DO*CI];     // center weights per r fp16
__device__ __align__(16) __half g_fmTh[CI*V];        // fm transposed [ci][p] fp16

// ------------------------- constants -------------------------
__constant__ float c_VS[12][3] = {
 {0.f, 0.5257311121f, 0.8506508084f},
 {0.f, 0.5257311121f,-0.8506508084f},
 {0.f,-0.5257311121f, 0.8506508084f},
 {0.f,-0.5257311121f,-0.8506508084f},
 { 0.5257311121f, 0.8506508084f,0.f},
 { 0.5257311121f,-0.8506508084f,0.f},
 {-0.5257311121f, 0.8506508084f,0.f},
 {-0.5257311121f,-0.8506508084f,0.f},
 { 0.8506508084f,0.f, 0.5257311121f},
 { 0.8506508084f,0.f,-0.5257311121f},
 {-0.8506508084f,0.f, 0.5257311121f},
 {-0.8506508084f,0.f,-0.5257311121f}};

__constant__ int c_C2V[6][2] = {{0,1},{6,7},{2,11},{4,9},{5,8},{3,10}};

__constant__ int c_INV[12][6] = {
 {0,1,2,3,4,5},{0,5,4,3,2,1},{4,3,0,5,2,1},{1,2,4,3,5,0},
 {3,5,2,0,4,1},{1,4,3,5,0,2},{4,0,3,1,2,5},{1,0,2,4,3,5},
 {4,1,2,5,0,3},{3,1,4,0,2,5},{2,1,4,5,3,0},{4,5,0,3,1,2}};

__constant__ int c_ROLL[5][6] = {
 {0,1,2,3,4,5},{0,2,3,4,5,1},{0,3,4,5,1,2},{0,4,5,1,2,3},{0,5,1,2,3,4}};

__device__ __forceinline__ float w13(const float* __restrict__ Wp, int k, int m) {
    if (k == 0)  return (m == 0) ? Wp[0] : Wp[1];
    if (k == 1)  return (m == 0) ? Wp[2] : Wp[3];
    if (k == 12) return (m == 0) ? Wp[4] : Wp[5];
    int pp = (k - 2) / 5, s = (k - 2) % 5;
    return Wp[6 + pp * 6 + c_ROLL[s][m]];
}

// ------------------------- K0: weight expansion + fm transpose -------------------------
__global__ void k0_weights(const float* __restrict__ W, const float* __restrict__ Wdir,
                           const float* __restrict__ fm) {
    const int N1 = ACT_ROWS * CI;          // 221184
    const int N2 = 144 * DO * CI;          // 1769472
    const int N3 = 12 * DO * CI;           // 147456
    const int N4 = CI * V;                 // 393216
    const int total = N1 + N2 + N3 + N4;
    for (int idx = blockIdx.x * blockDim.x + threadIdx.x; idx < total;
         idx += gridDim.x * blockDim.x) {
        if (idx < N1) {
            int ci = idx % CI, row = idx / CI;
            int r = row % 12, hk = row / 12, k = hk % 12, h = hk / 12;
            int c = ci / 6, i = ci % 6;
            // fold the 1/sqrt(dph)=0.5 logit scale into the weights
            g_Mh[idx] = __float2half_rn(0.5f * w13(Wdir + (h * DI + c) * 18, k, c_INV[r][i]));
        } else if (idx < N1 + N2) {
            int j = idx - N1;
            int ci = j % CI, dj = j / CI, d = dj % DO, kr = dj / DO;
            int r = kr % 12, k = kr / 12;
            g_Wfh[j] = __float2half_rn(w13(W + (d * DI + ci / 6) * 18, k, c_INV[r][ci % 6]));
        } else if (idx < N1 + N2 + N3) {
            int j = idx - N1 - N2;
            int ci = j % CI, dj = j / CI, d = dj % DO, r = dj / DO;
            g_Wch[j] = __float2half_rn(w13(W + (d * DI + ci / 6) * 18, 12, c_INV[r][ci % 6]));
        } else {
            int j = idx - N1 - N2 - N3;
            int p = j % V, ci = j / V;
            g_fmTh[j] = __float2half_rn(fm[((ci / 6) * V + p) * 6 + (ci % 6)]);
        }
    }
}

// ------------------------- K1: per-vertex cross features -------------------------
__global__ void k1_cross(const int* __restrict__ nbr, const float* __restrict__ verts,
                         const float* __restrict__ fm, const float* __restrict__ Wdim) {
    int p = blockIdx.x;
    int t = threadIdx.x;   // 192 threads
    __shared__ int   s_nbr[NB];
    __shared__ float s_cin[DI + 1][NB][6];
    __shared__ float s_wd[(DI + 1) * DI];
    if (t < NB) s_nbr[t] = nbr[p * NB + t];
    for (int x = t; x < (DI + 1) * DI; x += 192) s_wd[x] = Wdim[x];
    __syncthreads();
    if (t < NB) {
        int q = s_nbr[t];
        float cx = verts[p * 3], cy = verts[p * 3 + 1], cz = verts[p * 3 + 2];
        float dx = verts[q * 3] - cx, dy = verts[q * 3 + 1] - cy, dz = verts[q * 3 + 2] - cz;
        float nrm = fmaxf(sqrtf(dx * dx + dy * dy + dz * dz), 1e-12f);
        dx /= nrm; dy /= nrm; dz /= nrm;
        float de[12];
        #pragma unroll
        for (int v = 0; v < 12; v++)
            de[v] = c_VS[v][0] * dx + c_VS[v][1] * dy + c_VS[v][2] * dz;
        #pragma unroll
        for (int i = 0; i < 6; i++)
            s_cin[DI][t][i] = fmaxf(de[c_C2V[i][0]], de[c_C2V[i][1]]);
    }
    for (int x = t; x < DI * NB * 6; x += 192) {
        int c = x / (NB * 6), rem = x % (NB * 6), j = rem / 6, i = rem % 6;
        s_cin[c][j][i] = fm[(c * V + s_nbr[j]) * 6 + i];
    }
    __syncthreads();
    int o = t / 6, i = t % 6;
    for (int j = 0; j < NB; j++) {
        float a = 0.f;
        #pragma unroll
        for (int c = 0; c <= DI; c++) a += s_wd[c * DI + o] * s_cin[c][j][i];
        g_crossh[(size_t)(o * 6 + i) * NPJ + p * NB + j] = __float2half_rn(a);
    }
}

// ------------------------- K2: act logits GEMM + fused softmax ------------------------
// C(1152 x 32768) = Mh @ crossh. Block tile 128x128, 8 warps (2x4), warp 64x32.
// Smem-staged, double-buffered plain LDG->STS. Epilogue: per-warp C tile to smem,
// softmax over each 16-col neighbor group, write fp16 act.
__global__ __launch_bounds__(256) void k2_act() {
    extern __shared__ char dyn[];
    __half* sA = (__half*)dyn;             // [2][128][24]  (12288 B)
    __half* sB = (__half*)(dyn + 12288);   // [2][16][136]  ( 8704 B)
    float*  sC = (float*)dyn;              // [8][64][36]   (73728 B, reuse after loop)

    int m0 = blockIdx.y * 128, n0 = blockIdx.x * 128;
    int tid = threadIdx.x, lane = tid & 31, wid = tid >> 5;
    int wmL = (wid >> 2) * 64, wnL = (wid & 3) * 32;

    wmma::fragment<wmma::accumulator, 16, 16, 16, float> acc[4][2];
    #pragma unroll
    for (int i = 0; i < 4; i++)
        #pragma unroll
        for (int j = 0; j < 2; j++) wmma::fill_fragment(acc[i][j], 0.0f);

    int ar = tid >> 1, ac = (tid & 1) * 8;
    int br = tid >> 4, bc = (tid & 15) * 8;

    auto copyAB = [&](int kt, int buf) {
        int k0 = kt * 16;
        *(float4*)&sA[buf * 3072 + ar * 24 + ac] =
            *(const float4*)&g_Mh[(size_t)(m0 + ar) * CI + k0 + ac];
        *(float4*)&sB[buf * 2176 + br * 136 + bc] =
            *(const float4*)&g_crossh[(size_t)(k0 + br) * NPJ + n0 + bc];
    };

    copyAB(0, 0);
    __syncthreads();
    for (int kt = 0; kt < 12; kt++) {
        int buf = kt & 1;
        if (kt + 1 < 12) copyAB(kt + 1, buf ^ 1);
        wmma::fragment<wmma::matrix_a, 16, 16, 16, __half, wmma::row_major> af[4];
        wmma::fragment<wmma::matrix_b, 16, 16, 16, __half, wmma::row_major> bf[2];
        #pragma unroll
        for (int i = 0; i < 4; i++)
            wmma::load_matrix_sync(af[i], &sA[buf * 3072 + (wmL + i * 16) * 24], 24);
        #pragma unroll
        for (int j = 0; j < 2; j++)
            wmma::load_matrix_sync(bf[j], &sB[buf * 2176 + wnL + j * 16], 136);
        #pragma unroll
        for (int i = 0; i < 4; i++)
            #pragma unroll
            for (int j = 0; j < 2; j++)
                wmma::mma_sync(acc[i][j], af[i], bf[j], acc[i][j]);
        __syncthreads();
    }

    // --- fused softmax epilogue ---
    float* sCw = sC + wid * 64 * 36;       // per-warp 64x36 tile
    #pragma unroll
    for (int i = 0; i < 4; i++)
        #pragma unroll
        for (int j = 0; j < 2; j++)
            wmma::store_matrix_sync(&sCw[(i * 16) * 36 + j * 16], acc[i][j], 36,
                                    wmma::mem_row_major);
    __syncwarp();
    #pragma unroll
    for (int it = 0; it < 4; it++) {
        int g = lane + it * 32;            // 0..127 groups: 64 rows x 2 halves
        int row = g >> 1, half = g & 1;
        const float* src = &sCw[row * 36 + half * 16];
        float v[16];
        #pragma unroll
        for (int q = 0; q < 16; q++) v[q] = src[q];
        float mx = v[0];
        #pragma unroll
        for (int q = 1; q < 16; q++) mx = fmaxf(mx, v[q]);
        float s = 0.f;
        #pragma unroll
        for (int q = 0; q < 16; q++) { v[q] = __expf(v[q] - mx); s += v[q]; }
        float inv = 1.f / s;
        __align__(16) __half hv[16];
        #pragma unroll
        for (int q = 0; q < 16; q++) hv[q] = __float2half_rn(v[q] * inv);
        size_t off = (size_t)(m0 + wmL + row) * NPJ + n0 + wnL + half * 16;
        *(uint4*)&g_acth[off]     = *(uint4*)&hv[0];
        *(uint4*)&g_acth[off + 8] = *(uint4*)&hv[8];
    }
}

// ------------------------- K4a: nfm[(k,r)][ci][p] (fp16) = sum_j act*cross ------------
// One thread per p. grid (V/128, 12, 8) keyed on (p-tile, k, h). The 12 act rows
// for (h,k) are register-cached (two passes of 6 rows, fp32) and reused across
// all 24 ci of the head -> 24x less L1 act traffic, 16 FMA per output.
__global__ __launch_bounds__(128) void k4a_nfm() {
    int k = blockIdx.y;                    // 0..11
    int h = blockIdx.z;                    // 0..7
    int p = blockIdx.x * 128 + threadIdx.x;
    int abase = (h * 12 + k) * 12;
    #pragma unroll
    for (int rp = 0; rp < 2; rp++) {
        float av[6][16];
        #pragma unroll
        for (int rr = 0; rr < 6; rr++) {
            size_t aoff = (size_t)(abase + rp * 6 + rr) * NPJ + p * NB;
            uint4 a0 = *(const uint4*)&g_acth[aoff];
            uint4 a1 = *(const uint4*)&g_acth[aoff + 8];
            const __half2* h0 = (const __half2*)&a0;
            const __half2* h1 = (const __half2*)&a1;
            #pragma unroll
            for (int q = 0; q < 4; q++) {
                float2 f0 = __half22float2(h0[q]);
                float2 f1 = __half22float2(h1[q]);
                av[rr][q * 2] = f0.x;     av[rr][q * 2 + 1] = f0.y;
                av[rr][8 + q * 2] = f1.x; av[rr][8 + q * 2 + 1] = f1.y;
            }
        }
        #pragma unroll 4
        for (int cc = 0; cc < 24; cc++) {
            int ci = h * 24 + cc;
            size_t xoff = (size_t)ci * NPJ + p * NB;
            uint4 x0 = *(const uint4*)&g_crossh[xoff];
            uint4 x1 = *(const uint4*)&g_crossh[xoff + 8];
            const __half2* h0 = (const __half2*)&x0;
            const __half2* h1 = (const __half2*)&x1;
            float xv[16];
            #pragma unroll
            for (int q = 0; q < 4; q++) {
                float2 f0 = __half22float2(h0[q]);
                float2 f1 = __half22float2(h1[q]);
                xv[q * 2] = f0.x;     xv[q * 2 + 1] = f0.y;
                xv[8 + q * 2] = f1.x; xv[8 + q * 2 + 1] = f1.y;
            }
            #pragma unroll
            for (int rr = 0; rr < 6; rr++) {
                float acc = 0.f;
                #pragma unroll
                for (int q = 0; q < 16; q++) acc += av[rr][q] * xv[q];
                g_nfmh[((size_t)(k * 12 + rp * 6 + rr) * CI + ci) * V + p] =
                    __float2half_rn(acc);
            }
        }
    }
}

// ------------------------- K4b: ka[r] = sum over 13 slabs of W_slab @ B_slab ----------
// Per r: 12 x (Wf(k,r) 64x192 @ nfm(k,r) 192x2048) + Wc(r) @ fmT. Accum fp32 -> g_ka.
// grid (32, 12) = 384 CTAs, 128 threads = 4 warps; block tile 64 x 64, k-step 32,
// 78 double-buffered iterations, 8 MMAs/iter.
__global__ __launch_bounds__(128) void k4b_ka() {
    __shared__ __align__(16) __half sA[2][64][40];   // 64 x 32 (+8 pad)
    __shared__ __align__(16) __half sB[2][32][72];   // 32 x 64 (+8 pad)
    int r = blockIdx.y;
    int n0 = blockIdx.x * 64;
    int tid = threadIdx.x, wid = tid >> 5;
    int wn = wid * 16;

    wmma::fragment<wmma::accumulator, 16, 16, 16, float> acc[4];
    #pragma unroll
    for (int i = 0; i < 4; i++) wmma::fill_fragment(acc[i], 0.0f);

    auto aPtr = [&](int s) -> const __half* {
        return (s < 12) ? g_Wfh + (size_t)(s * 12 + r) * DO * CI
                        : g_Wch + (size_t)r * DO * CI;
    };
    auto bPtr = [&](int s) -> const __half* {
        return (s < 12) ? g_nfmh + (size_t)(s * 12 + r) * CI * V
                        : g_fmTh;
    };

    auto copyAB = [&](int it, int buf) {
        int s = it / 6, k0 = (it % 6) * 32;
        const __half* A = aPtr(s);
        const __half* B = bPtr(s);
        #pragma unroll
        for (int q = 0; q < 2; q++) {      // A: 64x32 = 256 float4, 2/thread
            int f = tid * 2 + q;
            int row = f >> 2, seg = (f & 3) * 8;
            *(float4*)&sA[buf][row][seg] = *(const float4*)&A[(size_t)row * CI + k0 + seg];
        }
        #pragma unroll
        for (int q = 0; q < 2; q++) {      // B: 32x64 = 256 float4, 2/thread
            int f = tid * 2 + q;
            int row = f >> 3, seg = (f & 7) * 8;
            *(float4*)&sB[buf][row][seg] = *(const float4*)&B[(size_t)(k0 + row) * V + n0 + seg];
        }
    };

    const int NIT = 13 * 6;    // 78
    copyAB(0, 0);
    __syncthreads();
    for (int it = 0; it < NIT; it++) {
        int buf = it & 1;
        if (it + 1 < NIT) copyAB(it + 1, buf ^ 1);
        #pragma unroll
        for (int kk = 0; kk < 2; kk++) {
            wmma::fragment<wmma::matrix_a, 16, 16, 16, __half, wmma::row_major> af[4];
            wmma::fragment<wmma::matrix_b, 16, 16, 16, __half, wmma::row_major> bf;
            #pragma unroll
            for (int i = 0; i < 4; i++)
                wmma::load_matrix_sync(af[i], &sA[buf][i * 16][kk * 16], 40);
            wmma::load_matrix_sync(bf, &sB[buf][kk * 16][wn], 72);
            #pragma unroll
            for (int i = 0; i < 4; i++)
                wmma::mma_sync(acc[i], af[i], bf, acc[i]);
        }
        __syncthreads();
    }
    #pragma unroll
    for (int i = 0; i < 4; i++)
        wmma::store_matrix_sync(g_ka + ((size_t)r * DO + i * 16) * V + n0 + wn,
                                acc[i], V, wmma::mem_row_major);
}

// ------------------------- K5: color-pair max + fm copy ----------------
__global__ void k5_final(const float* __restrict__ fm, float* __restrict__ out) {
    int idx = blockIdx.x * blockDim.x + threadIdx.x;
    const int NKA = DO * V;                // 131072
    if (idx < NKA) {
        int d = idx / V, p = idx % V;
        float ka[12];
        #pragma unroll
        for (int r = 0; r < 12; r++) ka[r] = g_ka[(size_t)(r * DO + d) * V + p];
        #pragma unroll
        for (int cc = 0; cc < 6; cc++)
            out[d * (V * 6) + p * 6 + cc] = fmaxf(ka[c_C2V[cc][0]], ka[c_C2V[cc][1]]);
    } else {
        int j = idx - NKA;
        if (j < DI * V * 6)
            out[DO * V * 6 + j] = fm[j];
    }
}

// ------------------------- launch -------------------------
extern "C" void kernel_launch(void* const* d_in, const int* in_sizes, int n_in,
                              void* d_out, int out_size) {
    const int*   nbr   = (const int*)d_in[0];
    const float* verts = (const float*)d_in[1];
    const float* fm    = (const float*)d_in[2];
    const float* Wdim  = (const float*)d_in[3];
    const float* W     = (const float*)d_in[4];
    const float* Wdir  = (const float*)d_in[5];
    float* out = (float*)d_out;

    const int K2_SMEM = 8 * 64 * 36 * 4;   // 73728 B (sC; covers sA+sB too)
    cudaFuncSetAttribute(k2_act, cudaFuncAttributeMaxDynamicSharedMemorySize, K2_SMEM);

    k0_weights<<<512, 256>>>(W, Wdir, fm);
    k1_cross<<<V, 192>>>(nbr, verts, fm, Wdim);
    k2_act<<<dim3(NPJ / 128, ACT_ROWS / 128), 256, K2_SMEM>>>();
    k4a_nfm<<<dim3(V / 128, 12, 8), 128>>>();
    k4b_ka<<<dim3(V / 64, 12), 128>>>();
    k5_final<<<(DO * V + DI * V * 6 + 255) / 256, 256>>>(fm, out);
}